// round 16
// baseline (speedup 1.0000x reference)
#include <cuda_runtime.h>

#define BATCH 2
#define NCAM  6
#define CH    128
#define IH    16
#define IW    44
#define ND    64
#define HW    (IH*IW)                 // 704
#define NPTS  (NCAM*ND*IH*IW)         // 270336
#define BEV_H 256
#define BEV_W 256
#define NBIN  (BEV_H*BEV_W)           // 65536
#define NTILE (NBIN/32)               // 2048
#define CAMSTRIDE (NCAM*ND*HW)
#define B1OFF  (NCAM*HW*CH)

#define PT_BLOCKS   (NPTS/256)        // 1056
#define TR_BLOCKS   ((CH/32)*(HW/32)*BATCH*NCAM)  // 1056
#define FILL_BLOCKS (NPTS/1024)       // 264

// Static scratch (allocation-free per harness rules)
__device__ float g_featT[(size_t)BATCH*NCAM*HW*CH];  // feat channel-last: (bn, hw, c)
__device__ int   g_bin[NPTS];
__device__ __align__(16) int g_cnt_i[NBIN];          // re-zeroed each run
__device__ __align__(16) int g_off[NBIN+1];
__device__ __align__(16) int g_wptr[NBIN];
__device__ int   g_bsum[64];
__device__ volatile int g_flag[64];                  // re-zeroed each run
__device__ int   g_sched[NTILE];                     // hot-first tile schedule
__device__ __align__(16) float4 g_list[NPTS];        // {fpix*CH as int, pad, d0, d1}

// ---------------------------------------------------------------------------
// In-block camera setup (geometry identical across batch; b=0 slices).
// ---------------------------------------------------------------------------
__device__ __forceinline__ void cam_setup(const float* __restrict__ intr,
                                          const float* __restrict__ extr,
                                          const int* __restrict__ pimg_h,
                                          const int* __restrict__ pimg_w,
                                          float* sKi, float* sRm, float* stv) {
    int n = threadIdx.x;
    if (n < NCAM) {
        float img_h = (float)pimg_h[0], img_w = (float)pimg_w[0];
        float sx = (float)IW / (img_w / 16.0f);
        float sy = (float)IH / (img_h / 16.0f);
        float rs0 = 16.0f / sx, rs1 = 16.0f / sy, rs2 = 1.0f;

        const float* Kp = intr + n*9;
        float a = Kp[0]*rs0, b = Kp[1]*rs0, c = Kp[2]*rs0;
        float d = Kp[3]*rs1, e = Kp[4]*rs1, f = Kp[5]*rs1;
        float g = Kp[6]*rs2, h = Kp[7]*rs2, i = Kp[8]*rs2;
        float A  = e*i - f*h;
        float Bc = -(d*i - f*g);
        float Cc = d*h - e*g;
        float det = a*A + b*Bc + c*Cc;
        float id = 1.0f / det;
        float* Ki = sKi + n*9;
        Ki[0] = A*id;             Ki[1] = (c*h - b*i)*id;  Ki[2] = (b*f - c*e)*id;
        Ki[3] = Bc*id;            Ki[4] = (a*i - c*g)*id;  Ki[5] = (c*d - a*f)*id;
        Ki[6] = Cc*id;            Ki[7] = (b*g - a*h)*id;  Ki[8] = (a*e - b*d)*id;

        const float* Ep = extr + n*16;
        #pragma unroll
        for (int r = 0; r < 3; r++) {
            #pragma unroll
            for (int cc = 0; cc < 3; cc++) sRm[n*9 + r*3+cc] = Ep[r*4+cc];
            stv[n*3 + r] = Ep[r*4+3];
        }
    }
}

// ---------------------------------------------------------------------------
// Fused kernel A: geometry (bin + warp-aggregated counts) + feat transpose.
// ---------------------------------------------------------------------------
__global__ void __launch_bounds__(256) pointA_kernel(
        const float* __restrict__ feat,
        const float* __restrict__ intr, const float* __restrict__ extr,
        const int* __restrict__ pimg_h, const int* __restrict__ pimg_w) {
    if (blockIdx.x < PT_BLOCKS) {
        __shared__ float sKi[NCAM*9], sRm[NCAM*9], stv[NCAM*3];
        cam_setup(intr, extr, pimg_h, pimg_w, sKi, sRm, stv);
        __syncthreads();

        int wp = blockIdx.x * 256 + threadIdx.x;
        int lane = threadIdx.x & 31;
        int w   = wp % IW;  int t = wp / IW;
        int h   = t % IH;   t /= IH;
        int dci = t % ND;
        int n   = t / ND;

        float dd = 1.0f + (59.0f / 63.0f) * (float)dci;  // linspace(1,60,64)
        float ux = (float)w * dd;
        float vy = (float)h * dd;

        const float* Ki = sKi + n*9;
        float pcx = Ki[0]*ux + Ki[1]*vy + Ki[2]*dd;
        float pcy = Ki[3]*ux + Ki[4]*vy + Ki[5]*dd;
        float pcz = Ki[6]*ux + Ki[7]*vy + Ki[8]*dd;

        const float* Rm = sRm + n*9;
        const float* tv = stv + n*3;
        float px = Rm[0]*pcx + Rm[1]*pcy + Rm[2]*pcz + tv[0];
        float py = Rm[3]*pcx + Rm[4]*pcy + Rm[5]*pcz + tv[1];
        float pz = Rm[6]*pcx + Rm[7]*pcy + Rm[8]*pcz + tv[2];

        int xi = (int)__fdiv_rn(px - (-51.2f), 0.4f);
        int yi = (int)__fdiv_rn(py - (-51.2f), 0.4f);
        bool valid = (xi >= 0) & (xi < BEV_W) & (yi >= 0) & (yi < BEV_H)
                   & (pz >= -5.0f) & (pz <= 3.0f);

        int bin = valid ? (yi * BEV_W + xi) : -1;
        g_bin[wp] = bin;
        unsigned mask = __match_any_sync(0xffffffffu, bin);
        if (bin >= 0) {
            int leader = __ffs(mask) - 1;
            if (lane == leader) atomicAdd(&g_cnt_i[bin], __popc(mask));
        }
    } else {
        __shared__ float tile[32][33];
        int tb  = blockIdx.x - PT_BLOCKS;
        int c0  = (tb & 3) * 32;
        int hw0 = ((tb >> 2) % 22) * 32;
        int bn  = tb / 88;
        int x = threadIdx.x & 31, y = threadIdx.x >> 5;
        const float* src = feat + (size_t)bn * CH * HW;
        #pragma unroll
        for (int k = 0; k < 4; k++)
            tile[y + k*8][x] = src[(size_t)(c0 + y + k*8) * HW + hw0 + x];
        __syncthreads();
        #pragma unroll
        for (int k = 0; k < 4; k++)
            g_featT[((size_t)bn * HW + hw0 + y + k*8) * CH + c0 + x] = tile[x][y + k*8];
    }
}

// ---------------------------------------------------------------------------
// Single-kernel scan: 64 blocks x 256 threads x int4 (all co-resident).
// ---------------------------------------------------------------------------
__global__ void __launch_bounds__(256) scan_kernel() {
    __shared__ int wsum[8], wexcl[8], sexcl[64];
    int t   = threadIdx.x;
    int bid = blockIdx.x;
    int gb  = bid * 1024 + t * 4;
    int4 c = *(const int4*)&g_cnt_i[gb];
    int s = c.x + c.y + c.z + c.w;
    int lane = t & 31, wid = t >> 5;
    int incl = s;
    #pragma unroll
    for (int d = 1; d < 32; d <<= 1) {
        int v = __shfl_up_sync(0xffffffffu, incl, d);
        if (lane >= d) incl += v;
    }
    if (lane == 31) wsum[wid] = incl;
    __syncthreads();
    if (t < 8) {
        int v = wsum[t];
        int iv = v;
        #pragma unroll
        for (int d = 1; d < 8; d <<= 1) {
            int u = __shfl_up_sync(0xffu, iv, d);
            if (t >= d) iv += u;
        }
        wexcl[t] = iv - v;
    }
    __syncthreads();
    int excl = incl - s + wexcl[wid];
    if (t == 255) {
        g_bsum[bid] = excl + s;
        __threadfence();
        g_flag[bid] = 1;
    }
    if (t < 64) {
        while (g_flag[t] == 0) { }
    }
    __syncthreads();
    __threadfence();
    if (t < 64) {
        int v = g_bsum[t];
        int iv = v;
        int l = t & 31;
        #pragma unroll
        for (int d = 1; d < 32; d <<= 1) {
            int u = __shfl_up_sync(0xffffffffu, iv, d);
            if (l >= d) iv += u;
        }
        if (t == 31) wsum[0] = iv;
        __syncwarp();
        sexcl[t] = iv - v;
    }
    __syncthreads();
    int base = sexcl[bid] + ((bid >= 32) ? wsum[0] : 0);
    int4 o;
    o.x = base + excl; o.y = o.x + c.x; o.z = o.y + c.y; o.w = o.z + c.z;
    *(int4*)&g_off[gb]  = o;
    *(int4*)&g_wptr[gb] = o;
    if (bid == 63 && t == 255) g_off[NBIN] = o.w + c.w;
}

// ---------------------------------------------------------------------------
// Fused kernel B: fill fat list (warp-aggregated cursors); extra block builds
// hot-first schedule over 2048 32-bin tiles + re-zeroes cnt/flags (coalesced).
// ---------------------------------------------------------------------------
__global__ void __launch_bounds__(1024) fillB_kernel(const float* __restrict__ depth) {
    int t = threadIdx.x;
    if (blockIdx.x < FILL_BLOCKS) {
        int wp = blockIdx.x * 1024 + t;
        int bin = g_bin[wp];
        int lane = t & 31;

        unsigned mask = __match_any_sync(0xffffffffu, bin);
        if (bin >= 0) {
            int leader = __ffs(mask) - 1;
            int rank = __popc(mask & ((1u << lane) - 1u));
            int pos0 = 0;
            if (lane == leader) pos0 = atomicAdd(&g_wptr[bin], __popc(mask));
            pos0 = __shfl_sync(mask, pos0, leader);

            int w   = wp % IW;  int q = wp / IW;
            int h   = q % IH;   q /= IH;
            int dci = q % ND;
            int n   = q / ND;
            int hw  = h * IW + w;
            int dpo = (n * ND + dci) * HW + hw;

            float4 e;
            e.x = __int_as_float((n * HW + hw) * CH);
            e.y = 0.f;
            e.z = __ldg(&depth[dpo]);
            e.w = __ldg(&depth[CAMSTRIDE + dpo]);
            g_list[pos0 + rank] = e;
        }
    } else {
        int4 z = {0, 0, 0, 0};
        #pragma unroll
        for (int j = 0; j < 16; j++)
            *(int4*)&g_cnt_i[(j * 1024 + t) * 4] = z;
        if (t < 64) *(int*)&g_flag[t] = 0;

        // hot-first schedule over 2048 tiles (2 per thread)
        __shared__ int bcnt[8], bbase[8];
        if (t < 8) bcnt[t] = 0;
        __syncthreads();
        int ks[2];
        #pragma unroll
        for (int j = 0; j < 2; j++) {
            int tile = t + j * 1024;
            int cnt = g_off[tile*32 + 32] - g_off[tile*32];
            int k = cnt > 4096 ? 0 : cnt > 2048 ? 1 : cnt > 1024 ? 2 : cnt > 512 ? 3 :
                    cnt > 256  ? 4 : cnt > 128  ? 5 : cnt > 64   ? 6 : 7;
            ks[j] = k;
            atomicAdd(&bcnt[k], 1);
        }
        __syncthreads();
        if (t == 0) {
            int r = 0;
            #pragma unroll
            for (int k = 0; k < 8; k++) { bbase[k] = r; r += bcnt[k]; }
        }
        __syncthreads();
        #pragma unroll
        for (int j = 0; j < 2; j++) {
            int pos = atomicAdd(&bbase[ks[j]], 1);
            g_sched[pos] = t + j * 1024;
        }
    }
}

// ---------------------------------------------------------------------------
// Channel-interleaved accumulate: lane l owns channels {l, l+32, l+64, l+96}.
// Feat loads: 8 scalar LDG.32 per point, each warp-instruction 128B coalesced.
// a[0..3] = batch0 channels l+32j; a[4..7] = batch1 channels l+32j.
// ---------------------------------------------------------------------------
__device__ __forceinline__ void accum_run(int beg, int end, int lane, float* a) {
    for (int base = beg; base < end; base += 32) {
        int m = end - base;  if (m > 32) m = 32;
        float4 e = {0.f, 0.f, 0.f, 0.f};
        if (lane < m) e = g_list[base + lane];
        int fo = __float_as_int(e.x);

        #pragma unroll 4
        for (int j = 0; j < m; j++) {
            int   foff = __shfl_sync(0xffffffffu, fo,  j);
            float d0   = __shfl_sync(0xffffffffu, e.z, j);
            float d1   = __shfl_sync(0xffffffffu, e.w, j);
            const float* p0 = g_featT + foff + lane;
            const float* p1 = p0 + B1OFF;
            float v0 = p0[0],  v1 = p0[32], v2 = p0[64], v3 = p0[96];
            float w0 = p1[0],  w1 = p1[32], w2 = p1[64], w3 = p1[96];
            a[0] += v0 * d0;  a[1] += v1 * d0;  a[2] += v2 * d0;  a[3] += v3 * d0;
            a[4] += w0 * d1;  a[5] += w1 * d1;  a[6] += w2 * d1;  a[7] += w3 * d1;
        }
    }
}

// ---------------------------------------------------------------------------
// Gather: block = 32-bin tile (hot-first), 8 warps, warp owns 4 bins.
// Lane<->channel mapping is interleaved so BOTH smem directions are
// conflict-free at ACCW=129: phase-1 stores / phase-2 atomics hit addr
// bl*129 + lane + 32j (lane-stride 1); epilogue reads acc[b][lane][c]
// (lane-stride 129 === 1 mod 32). Pre-scaled accumulators -> epilogue is a
// bare LDS + coalesced 128B STG.
// ---------------------------------------------------------------------------
#define CAP    32
#define CHUNK  64
#define MAXQ   512
#define ACCW   129
__global__ void __launch_bounds__(256) gather_kernel(float* __restrict__ out) {
    __shared__ float acc[BATCH][32][ACCW];
    __shared__ float sinv[32];
    __shared__ int   cq[MAXQ];               // bl<<26 | len<<19 | beg
    __shared__ int   sQn, sCtr;

    int tile = g_sched[blockIdx.x];
    int bin0 = tile * 32;
    int tid  = threadIdx.x;
    int warp = tid >> 5;
    int lane = tid & 31;

    if (tid == 0) { sQn = 0; sCtr = 0; }
    __syncthreads();

    // ---- Phase 1: exclusive ownership of 4 bins, first <=CAP points each ----
    #pragma unroll
    for (int k = 0; k < 4; k++) {
        int bl  = warp + k * 8;
        int bin = bin0 + bl;
        int beg = g_off[bin];
        int end = g_off[bin + 1];
        int cnt = end - beg;
        float inv = __fdiv_rn(1.0f, (float)cnt + 1e-5f);
        if (lane == 0) sinv[bl] = inv;

        int p1 = cnt < CAP ? cnt : CAP;
        float a[8] = {0.f, 0.f, 0.f, 0.f, 0.f, 0.f, 0.f, 0.f};
        accum_run(beg, beg + p1, lane, a);

        // conflict-free scalar stores: addr = bl*129 + lane + 32j
        #pragma unroll
        for (int j = 0; j < 4; j++) {
            acc[0][bl][lane + 32*j] = a[j]     * inv;
            acc[1][bl][lane + 32*j] = a[4 + j] * inv;
        }

        if (cnt > CAP && lane == 0) {
            int rem = cnt - CAP;
            int nch = (rem + CHUNK - 1) / CHUNK;
            if (nch > 15) nch = 15;
            int cl = (rem + nch - 1) / nch;
            int qb = atomicAdd(&sQn, nch);
            int b0 = beg + CAP;
            for (int j = 0; j < nch; j++) {
                int l = rem - j * cl; if (l > cl) l = cl;
                cq[qb + j] = (bl << 26) | (l << 19) | (b0 + j * cl);
            }
        }
    }
    __syncthreads();

    // ---- Phase 2: steal remainder chunks of hot bins (conflict-free flush) --
    int total = sQn;
    while (true) {
        int cidx;
        if (lane == 0) cidx = atomicAdd(&sCtr, 1);
        cidx = __shfl_sync(0xffffffffu, cidx, 0);
        if (cidx >= total) break;

        int e   = cq[cidx];
        int bl  = e >> 26;
        int len = (e >> 19) & 0x7F;
        int beg = e & 0x7FFFF;
        float a[8] = {0.f, 0.f, 0.f, 0.f, 0.f, 0.f, 0.f, 0.f};
        accum_run(beg, beg + len, lane, a);

        float inv = sinv[bl];
        #pragma unroll
        for (int j = 0; j < 4; j++) {
            atomicAdd(&acc[0][bl][lane + 32*j], a[j]     * inv);
            atomicAdd(&acc[1][bl][lane + 32*j], a[4 + j] * inv);
        }
    }
    __syncthreads();

    // ---- Epilogue: 256 rows (b,c), 32 consecutive bins -> 128B stores ----
    #pragma unroll
    for (int r = warp; r < BATCH * CH; r += 8) {
        int b = r >> 7;
        int c = r & 127;
        out[((size_t)(b * CH + c)) * NBIN + bin0 + lane] = acc[b][lane][c];
    }
}

extern "C" void kernel_launch(void* const* d_in, const int* in_sizes, int n_in,
                              void* d_out, int out_size) {
    const float* feat  = (const float*)d_in[0];
    const float* depth = (const float*)d_in[1];
    const float* intr  = (const float*)d_in[2];
    const float* extr  = (const float*)d_in[3];
    const int*   img_h = (const int*)d_in[4];
    const int*   img_w = (const int*)d_in[5];
    float* out = (float*)d_out;

    pointA_kernel<<<PT_BLOCKS + TR_BLOCKS, 256>>>(feat, intr, extr, img_h, img_w);
    scan_kernel<<<64, 256>>>();
    fillB_kernel<<<FILL_BLOCKS + 1, 1024>>>(depth);
    gather_kernel<<<NTILE, 256>>>(out);
}

// round 17
// speedup vs baseline: 1.8261x; 1.8261x over previous
#include <cuda_runtime.h>
#include <cuda_fp16.h>

#define BATCH 2
#define NCAM  6
#define CH    128
#define IH    16
#define IW    44
#define ND    64
#define HW    (IH*IW)                 // 704
#define NPTS  (NCAM*ND*IH*IW)         // 270336
#define BEV_H 256
#define BEV_W 256
#define NBIN  (BEV_H*BEV_W)           // 65536
#define NTILE (NBIN/32)               // 2048
#define CAMSTRIDE (NCAM*ND*HW)
#define B1OFF  (NCAM*HW*CH)           // featT offset of batch 1 (elements)

#define PT_BLOCKS   (NPTS/256)        // 1056
#define TR_BLOCKS   ((CH/32)*(HW/32)*BATCH*NCAM)  // 1056
#define FILL_BLOCKS (NPTS/1024)       // 264

// Static scratch (allocation-free per harness rules)
__device__ __half g_featT[(size_t)BATCH*NCAM*HW*CH]; // feat channel-last, fp16
__device__ int   g_bin[NPTS];
__device__ __align__(16) int g_cnt_i[NBIN];          // re-zeroed each run
__device__ __align__(16) int g_off[NBIN+1];
__device__ __align__(16) int g_wptr[NBIN];
__device__ int   g_bsum[64];
__device__ volatile int g_flag[64];                  // re-zeroed each run
__device__ int   g_sched[NTILE];                     // hot-first tile schedule
__device__ __align__(16) float4 g_list[NPTS];        // {fpix*CH as int, pad, d0, d1}

// ---------------------------------------------------------------------------
// In-block camera setup (geometry identical across batch; b=0 slices).
// ---------------------------------------------------------------------------
__device__ __forceinline__ void cam_setup(const float* __restrict__ intr,
                                          const float* __restrict__ extr,
                                          const int* __restrict__ pimg_h,
                                          const int* __restrict__ pimg_w,
                                          float* sKi, float* sRm, float* stv) {
    int n = threadIdx.x;
    if (n < NCAM) {
        float img_h = (float)pimg_h[0], img_w = (float)pimg_w[0];
        float sx = (float)IW / (img_w / 16.0f);
        float sy = (float)IH / (img_h / 16.0f);
        float rs0 = 16.0f / sx, rs1 = 16.0f / sy, rs2 = 1.0f;

        const float* Kp = intr + n*9;
        float a = Kp[0]*rs0, b = Kp[1]*rs0, c = Kp[2]*rs0;
        float d = Kp[3]*rs1, e = Kp[4]*rs1, f = Kp[5]*rs1;
        float g = Kp[6]*rs2, h = Kp[7]*rs2, i = Kp[8]*rs2;
        float A  = e*i - f*h;
        float Bc = -(d*i - f*g);
        float Cc = d*h - e*g;
        float det = a*A + b*Bc + c*Cc;
        float id = 1.0f / det;
        float* Ki = sKi + n*9;
        Ki[0] = A*id;             Ki[1] = (c*h - b*i)*id;  Ki[2] = (b*f - c*e)*id;
        Ki[3] = Bc*id;            Ki[4] = (a*i - c*g)*id;  Ki[5] = (c*d - a*f)*id;
        Ki[6] = Cc*id;            Ki[7] = (b*g - a*h)*id;  Ki[8] = (a*e - b*d)*id;

        const float* Ep = extr + n*16;
        #pragma unroll
        for (int r = 0; r < 3; r++) {
            #pragma unroll
            for (int cc = 0; cc < 3; cc++) sRm[n*9 + r*3+cc] = Ep[r*4+cc];
            stv[n*3 + r] = Ep[r*4+3];
        }
    }
}

// ---------------------------------------------------------------------------
// Fused kernel A: geometry (bin + warp-aggregated counts) + feat transpose
// with fused fp32 -> fp16 conversion.
// ---------------------------------------------------------------------------
__global__ void __launch_bounds__(256) pointA_kernel(
        const float* __restrict__ feat,
        const float* __restrict__ intr, const float* __restrict__ extr,
        const int* __restrict__ pimg_h, const int* __restrict__ pimg_w) {
    if (blockIdx.x < PT_BLOCKS) {
        __shared__ float sKi[NCAM*9], sRm[NCAM*9], stv[NCAM*3];
        cam_setup(intr, extr, pimg_h, pimg_w, sKi, sRm, stv);
        __syncthreads();

        int wp = blockIdx.x * 256 + threadIdx.x;
        int lane = threadIdx.x & 31;
        int w   = wp % IW;  int t = wp / IW;
        int h   = t % IH;   t /= IH;
        int dci = t % ND;
        int n   = t / ND;

        float dd = 1.0f + (59.0f / 63.0f) * (float)dci;  // linspace(1,60,64)
        float ux = (float)w * dd;
        float vy = (float)h * dd;

        const float* Ki = sKi + n*9;
        float pcx = Ki[0]*ux + Ki[1]*vy + Ki[2]*dd;
        float pcy = Ki[3]*ux + Ki[4]*vy + Ki[5]*dd;
        float pcz = Ki[6]*ux + Ki[7]*vy + Ki[8]*dd;

        const float* Rm = sRm + n*9;
        const float* tv = stv + n*3;
        float px = Rm[0]*pcx + Rm[1]*pcy + Rm[2]*pcz + tv[0];
        float py = Rm[3]*pcx + Rm[4]*pcy + Rm[5]*pcz + tv[1];
        float pz = Rm[6]*pcx + Rm[7]*pcy + Rm[8]*pcz + tv[2];

        int xi = (int)__fdiv_rn(px - (-51.2f), 0.4f);
        int yi = (int)__fdiv_rn(py - (-51.2f), 0.4f);
        bool valid = (xi >= 0) & (xi < BEV_W) & (yi >= 0) & (yi < BEV_H)
                   & (pz >= -5.0f) & (pz <= 3.0f);

        int bin = valid ? (yi * BEV_W + xi) : -1;
        g_bin[wp] = bin;
        unsigned mask = __match_any_sync(0xffffffffu, bin);
        if (bin >= 0) {
            int leader = __ffs(mask) - 1;
            if (lane == leader) atomicAdd(&g_cnt_i[bin], __popc(mask));
        }
    } else {
        __shared__ float tile[32][33];
        int tb  = blockIdx.x - PT_BLOCKS;
        int c0  = (tb & 3) * 32;
        int hw0 = ((tb >> 2) % 22) * 32;
        int bn  = tb / 88;
        int x = threadIdx.x & 31, y = threadIdx.x >> 5;
        const float* src = feat + (size_t)bn * CH * HW;
        #pragma unroll
        for (int k = 0; k < 4; k++)
            tile[y + k*8][x] = src[(size_t)(c0 + y + k*8) * HW + hw0 + x];
        __syncthreads();
        #pragma unroll
        for (int k = 0; k < 4; k++)
            g_featT[((size_t)bn * HW + hw0 + y + k*8) * CH + c0 + x] =
                __float2half(tile[x][y + k*8]);
    }
}

// ---------------------------------------------------------------------------
// Single-kernel scan: 64 blocks x 256 threads x int4 (all co-resident).
// ---------------------------------------------------------------------------
__global__ void __launch_bounds__(256) scan_kernel() {
    __shared__ int wsum[8], wexcl[8], sexcl[64];
    int t   = threadIdx.x;
    int bid = blockIdx.x;
    int gb  = bid * 1024 + t * 4;
    int4 c = *(const int4*)&g_cnt_i[gb];
    int s = c.x + c.y + c.z + c.w;
    int lane = t & 31, wid = t >> 5;
    int incl = s;
    #pragma unroll
    for (int d = 1; d < 32; d <<= 1) {
        int v = __shfl_up_sync(0xffffffffu, incl, d);
        if (lane >= d) incl += v;
    }
    if (lane == 31) wsum[wid] = incl;
    __syncthreads();
    if (t < 8) {
        int v = wsum[t];
        int iv = v;
        #pragma unroll
        for (int d = 1; d < 8; d <<= 1) {
            int u = __shfl_up_sync(0xffu, iv, d);
            if (t >= d) iv += u;
        }
        wexcl[t] = iv - v;
    }
    __syncthreads();
    int excl = incl - s + wexcl[wid];
    if (t == 255) {
        g_bsum[bid] = excl + s;
        __threadfence();
        g_flag[bid] = 1;
    }
    if (t < 64) {
        while (g_flag[t] == 0) { }
    }
    __syncthreads();
    __threadfence();
    if (t < 64) {
        int v = g_bsum[t];
        int iv = v;
        int l = t & 31;
        #pragma unroll
        for (int d = 1; d < 32; d <<= 1) {
            int u = __shfl_up_sync(0xffffffffu, iv, d);
            if (l >= d) iv += u;
        }
        if (t == 31) wsum[0] = iv;
        __syncwarp();
        sexcl[t] = iv - v;
    }
    __syncthreads();
    int base = sexcl[bid] + ((bid >= 32) ? wsum[0] : 0);
    int4 o;
    o.x = base + excl; o.y = o.x + c.x; o.z = o.y + c.y; o.w = o.z + c.z;
    *(int4*)&g_off[gb]  = o;
    *(int4*)&g_wptr[gb] = o;
    if (bid == 63 && t == 255) g_off[NBIN] = o.w + c.w;
}

// ---------------------------------------------------------------------------
// Fused kernel B: fill fat list (warp-aggregated cursors); extra block builds
// hot-first schedule + re-zeroes cnt/flags (coalesced).
// ---------------------------------------------------------------------------
__global__ void __launch_bounds__(1024) fillB_kernel(const float* __restrict__ depth) {
    int t = threadIdx.x;
    if (blockIdx.x < FILL_BLOCKS) {
        int wp = blockIdx.x * 1024 + t;
        int bin = g_bin[wp];
        int lane = t & 31;

        unsigned mask = __match_any_sync(0xffffffffu, bin);
        if (bin >= 0) {
            int leader = __ffs(mask) - 1;
            int rank = __popc(mask & ((1u << lane) - 1u));
            int pos0 = 0;
            if (lane == leader) pos0 = atomicAdd(&g_wptr[bin], __popc(mask));
            pos0 = __shfl_sync(mask, pos0, leader);

            int w   = wp % IW;  int q = wp / IW;
            int h   = q % IH;   q /= IH;
            int dci = q % ND;
            int n   = q / ND;
            int hw  = h * IW + w;
            int dpo = (n * ND + dci) * HW + hw;

            float4 e;
            e.x = __int_as_float((n * HW + hw) * CH);
            e.y = 0.f;
            e.z = __ldg(&depth[dpo]);
            e.w = __ldg(&depth[CAMSTRIDE + dpo]);
            g_list[pos0 + rank] = e;
        }
    } else {
        int4 z = {0, 0, 0, 0};
        #pragma unroll
        for (int j = 0; j < 16; j++)
            *(int4*)&g_cnt_i[(j * 1024 + t) * 4] = z;
        if (t < 64) *(int*)&g_flag[t] = 0;

        __shared__ int bcnt[8], bbase[8];
        if (t < 8) bcnt[t] = 0;
        __syncthreads();
        int ks[2];
        #pragma unroll
        for (int j = 0; j < 2; j++) {
            int tile = t + j * 1024;
            int cnt = g_off[tile*32 + 32] - g_off[tile*32];
            int k = cnt > 4096 ? 0 : cnt > 2048 ? 1 : cnt > 1024 ? 2 : cnt > 512 ? 3 :
                    cnt > 256  ? 4 : cnt > 128  ? 5 : cnt > 64   ? 6 : 7;
            ks[j] = k;
            atomicAdd(&bcnt[k], 1);
        }
        __syncthreads();
        if (t == 0) {
            int r = 0;
            #pragma unroll
            for (int k = 0; k < 8; k++) { bbase[k] = r; r += bcnt[k]; }
        }
        __syncthreads();
        #pragma unroll
        for (int j = 0; j < 2; j++) {
            int pos = atomicAdd(&bbase[ks[j]], 1);
            g_sched[pos] = t + j * 1024;
        }
    }
}

// ---------------------------------------------------------------------------
// Per-point accumulate: 2x LDG.64 (fp16 feat rows) + h2->f2 cvt + fp32 FMA.
// Lane l handles channels [4l, 4l+4).
// ---------------------------------------------------------------------------
__device__ __forceinline__ void fma_point(int foff, float d0, float d1, int lane,
                                          float* a) {
    const __half* p0 = g_featT + foff;
    uint2 v0 = *((const uint2*)p0 + lane);
    uint2 v1 = *((const uint2*)(p0 + B1OFF) + lane);
    const __half2* q0 = (const __half2*)&v0;
    const __half2* q1 = (const __half2*)&v1;
    float2 x0 = __half22float2(q0[0]);
    float2 x1 = __half22float2(q0[1]);
    float2 y0 = __half22float2(q1[0]);
    float2 y1 = __half22float2(q1[1]);
    a[0] += x0.x * d0;  a[1] += x0.y * d0;  a[2] += x1.x * d0;  a[3] += x1.y * d0;
    a[4] += y0.x * d1;  a[5] += y0.y * d1;  a[6] += y1.x * d1;  a[7] += y1.y * d1;
}

// Generic run (phase 2): lane-parallel list prefetch + shuffle broadcast.
__device__ __forceinline__ void accum_run(int beg, int end, int lane, float* a) {
    for (int base = beg; base < end; base += 32) {
        int m = end - base;  if (m > 32) m = 32;
        float4 e = {0.f, 0.f, 0.f, 0.f};
        if (lane < m) e = g_list[base + lane];
        int fo = __float_as_int(e.x);
        #pragma unroll 4
        for (int j = 0; j < m; j++) {
            int   foff = __shfl_sync(0xffffffffu, fo,  j);
            float d0   = __shfl_sync(0xffffffffu, e.z, j);
            float d1   = __shfl_sync(0xffffffffu, e.w, j);
            fma_point(foff, d0, d1, lane, a);
        }
    }
}

// ---------------------------------------------------------------------------
// Gather (round-12 structure): block = 32-bin tile (hot-first), 8 warps, warp
// owns 4 bins; all 4 owned bins' list entries preloaded up front so their
// load latencies overlap. Phase 2: packed-queue chunk stealing for hot bins.
// Epilogue: reciprocal * (bin,c)->(c,bin) transpose, coalesced STG.
// ---------------------------------------------------------------------------
#define CAP    32
#define CHUNK  64
#define MAXQ   512
__global__ void __launch_bounds__(256) gather_kernel(float* __restrict__ out) {
    __shared__ float acc[BATCH][32][CH + 1];
    __shared__ float sinv[32];
    __shared__ int   cq[MAXQ];               // bl<<26 | len<<19 | beg
    __shared__ int   sQn, sCtr;

    int tile = g_sched[blockIdx.x];
    int bin0 = tile * 32;
    int tid  = threadIdx.x;
    int warp = tid >> 5;
    int lane = tid & 31;

    if (tid == 0) { sQn = 0; sCtr = 0; }
    __syncthreads();

    // ---- Phase 1: preload all 4 owned bins' list entries, then process ----
    int    begA[4], cntA[4];
    float4 ent[4];
    #pragma unroll
    for (int k = 0; k < 4; k++) {
        int bin = bin0 + warp + k * 8;
        int beg = g_off[bin];
        int end = g_off[bin + 1];
        int cnt = end - beg;
        begA[k] = beg;  cntA[k] = cnt;
        if (lane == 0) sinv[warp + k*8] = __fdiv_rn(1.0f, (float)cnt + 1e-5f);
        int m = cnt < CAP ? cnt : CAP;
        float4 e = {0.f, 0.f, 0.f, 0.f};
        if (lane < m) e = g_list[beg + lane];   // 4 independent LDG.128s
        ent[k] = e;
    }

    #pragma unroll
    for (int k = 0; k < 4; k++) {
        int bl  = warp + k * 8;
        int cnt = cntA[k];
        int m   = cnt < CAP ? cnt : CAP;
        int fo  = __float_as_int(ent[k].x);

        float a[8] = {0.f, 0.f, 0.f, 0.f, 0.f, 0.f, 0.f, 0.f};
        #pragma unroll 4
        for (int j = 0; j < m; j++) {
            int   foff = __shfl_sync(0xffffffffu, fo,       j);
            float d0   = __shfl_sync(0xffffffffu, ent[k].z, j);
            float d1   = __shfl_sync(0xffffffffu, ent[k].w, j);
            fma_point(foff, d0, d1, lane, a);
        }

        int c4 = lane * 4;
        acc[0][bl][c4+0] = a[0];  acc[0][bl][c4+1] = a[1];
        acc[0][bl][c4+2] = a[2];  acc[0][bl][c4+3] = a[3];
        acc[1][bl][c4+0] = a[4];  acc[1][bl][c4+1] = a[5];
        acc[1][bl][c4+2] = a[6];  acc[1][bl][c4+3] = a[7];

        if (cnt > CAP && lane == 0) {
            int rem = cnt - CAP;
            int nch = (rem + CHUNK - 1) / CHUNK;
            if (nch > 15) nch = 15;
            int cl = (rem + nch - 1) / nch;
            int qb = atomicAdd(&sQn, nch);
            int b0 = begA[k] + CAP;
            for (int j = 0; j < nch; j++) {
                int l = rem - j * cl; if (l > cl) l = cl;
                cq[qb + j] = (bl << 26) | (l << 19) | (b0 + j * cl);
            }
        }
    }
    __syncthreads();

    // ---- Phase 2: steal remainder chunks of hot bins ----
    int total = sQn;
    while (true) {
        int cidx;
        if (lane == 0) cidx = atomicAdd(&sCtr, 1);
        cidx = __shfl_sync(0xffffffffu, cidx, 0);
        if (cidx >= total) break;

        int e   = cq[cidx];
        int bl  = e >> 26;
        int len = (e >> 19) & 0x7F;
        int beg = e & 0x7FFFF;
        float a[8] = {0.f, 0.f, 0.f, 0.f, 0.f, 0.f, 0.f, 0.f};
        accum_run(beg, beg + len, lane, a);

        int c4 = lane * 4;
        atomicAdd(&acc[0][bl][c4+0], a[0]);  atomicAdd(&acc[0][bl][c4+1], a[1]);
        atomicAdd(&acc[0][bl][c4+2], a[2]);  atomicAdd(&acc[0][bl][c4+3], a[3]);
        atomicAdd(&acc[1][bl][c4+0], a[4]);  atomicAdd(&acc[1][bl][c4+1], a[5]);
        atomicAdd(&acc[1][bl][c4+2], a[6]);  atomicAdd(&acc[1][bl][c4+3], a[7]);
    }
    __syncthreads();

    // ---- Epilogue: 256 rows (b,c), 32 consecutive bins -> 128B stores ----
    #pragma unroll
    for (int r = warp; r < BATCH * CH; r += 8) {
        int b = r >> 7;
        int c = r & 127;
        float v = acc[b][lane][c];               // stride-129: conflict-free
        out[((size_t)(b * CH + c)) * NBIN + bin0 + lane] = v * sinv[lane];
    }
}

extern "C" void kernel_launch(void* const* d_in, const int* in_sizes, int n_in,
                              void* d_out, int out_size) {
    const float* feat  = (const float*)d_in[0];
    const float* depth = (const float*)d_in[1];
    const float* intr  = (const float*)d_in[2];
    const float* extr  = (const float*)d_in[3];
    const int*   img_h = (const int*)d_in[4];
    const int*   img_w = (const int*)d_in[5];
    float* out = (float*)d_out;

    pointA_kernel<<<PT_BLOCKS + TR_BLOCKS, 256>>>(feat, intr, extr, img_h, img_w);
    scan_kernel<<<64, 256>>>();
    fillB_kernel<<<FILL_BLOCKS + 1, 1024>>>(depth);
    gather_kernel<<<NTILE, 256>>>(out);
}